// round 1
// baseline (speedup 1.0000x reference)
#include <cuda_runtime.h>
#include <cstdint>

#define BB 2
#define CIN 64
#define HIN 128
#define WIN 256
#define COUTN 64
#define KK 9
#define HO 128
#define WO 256
#define HWIN (HIN*WIN)
#define HWO (HO*WO)
#define CHALF 32           // couts per block
#define SMEM_BYTES (CIN*KK*CHALF*4)   // 576*32*4 = 73728

extern __shared__ float s_w[];   // [576][32] : s_w[(c*9+k)*32 + cout_local]

__global__ __launch_bounds__(256, 2)
void dcn_kernel(const float* __restrict__ x, const float* __restrict__ off,
                const float* __restrict__ weight, const float* __restrict__ bias,
                float* __restrict__ out)
{
    const int tid    = threadIdx.x;
    const int half   = blockIdx.x & 1;          // which cout half
    const int pixblk = blockIdx.x >> 1;         // [0,256): one output row
    const int cout0  = half * CHALF;

    // Stage transposed weights into shared: s_w[ck*32 + cl] = W[cout0+cl][ck]
    for (int i = tid; i < CIN*KK*CHALF; i += 256) {
        int cl = i / (CIN*KK);
        int ck = i % (CIN*KK);
        s_w[ck*CHALF + cl] = weight[(cout0 + cl)*(CIN*KK) + ck];
    }
    __syncthreads();

    const int wo = tid;                 // 256 threads = full row of wo
    const int ho = pixblk & (HO-1);
    const int b  = pixblk >> 7;

    const float* xb   = x + (size_t)b * (CIN*HWIN);
    const float* offp = off + (size_t)b * (2*KK*HWO) + ho*WO + wo;

    unsigned long long acc[CHALF/2];
    #pragma unroll
    for (int j = 0; j < CHALF/2; j++) acc[j] = 0ULL;

    #pragma unroll
    for (int k = 0; k < KK; k++) {
        const int ki = k / 3, kj = k % 3;
        const float oy = offp[(2*k  )*HWO];
        const float ox = offp[(2*k+1)*HWO];
        const float py = (float)(ho - 1 + ki) + oy;
        const float px = (float)(wo - 1 + kj) + ox;
        const float y0f = floorf(py), x0f = floorf(px);
        const float wy = py - y0f,   wx = px - x0f;
        const int y0 = (int)y0f, x0 = (int)x0f;
        const int y1 = y0 + 1,   x1 = x0 + 1;
        const float vy0 = (y0 >= 0 && y0 < HIN) ? 1.f : 0.f;
        const float vy1 = (y1 >= 0 && y1 < HIN) ? 1.f : 0.f;
        const float vx0 = (x0 >= 0 && x0 < WIN) ? 1.f : 0.f;
        const float vx1 = (x1 >= 0 && x1 < WIN) ? 1.f : 0.f;
        const int ya = min(max(y0, 0), HIN-1), ybb = min(max(y1, 0), HIN-1);
        const int xa = min(max(x0, 0), WIN-1), xbb = min(max(x1, 0), WIN-1);
        const float w00 = (1.f-wy)*(1.f-wx)*vy0*vx0;
        const float w01 = (1.f-wy)*wx      *vy0*vx1;
        const float w10 = wy      *(1.f-wx)*vy1*vx0;
        const float w11 = wy      *wx      *vy1*vx1;
        const float* p00 = xb + ya *WIN + xa;
        const float* p01 = xb + ya *WIN + xbb;
        const float* p10 = xb + ybb*WIN + xa;
        const float* p11 = xb + ybb*WIN + xbb;

        #pragma unroll 2
        for (int c = 0; c < CIN; c++) {
            float s = w00 * __ldg(p00 + c*HWIN)
                    + w01 * __ldg(p01 + c*HWIN)
                    + w10 * __ldg(p10 + c*HWIN)
                    + w11 * __ldg(p11 + c*HWIN);
            unsigned int su = __float_as_uint(s);
            unsigned long long s2;
            asm("mov.b64 %0, {%1, %1};" : "=l"(s2) : "r"(su));
            const ulonglong2* wr = (const ulonglong2*)(s_w + (c*KK + k)*CHALF);
            #pragma unroll
            for (int j = 0; j < CHALF/4; j++) {
                ulonglong2 wv = wr[j];
                asm("fma.rn.f32x2 %0, %1, %2, %0;" : "+l"(acc[2*j  ]) : "l"(wv.x), "l"(s2));
                asm("fma.rn.f32x2 %0, %1, %2, %0;" : "+l"(acc[2*j+1]) : "l"(wv.y), "l"(s2));
            }
        }
    }

    float* op = out + (size_t)b*(COUTN*HWO) + (size_t)cout0*HWO + ho*WO + wo;
    #pragma unroll
    for (int j = 0; j < CHALF/2; j++) {
        float a0 = __uint_as_float((unsigned)(acc[j] & 0xffffffffULL)) + bias[cout0 + 2*j];
        float a1 = __uint_as_float((unsigned)(acc[j] >> 32))           + bias[cout0 + 2*j + 1];
        op[(2*j  )*HWO] = a0;
        op[(2*j+1)*HWO] = a1;
    }
}

extern "C" void kernel_launch(void* const* d_in, const int* in_sizes, int n_in,
                              void* d_out, int out_size) {
    const float* x    = (const float*)d_in[0];
    const float* off  = (const float*)d_in[1];
    const float* w    = (const float*)d_in[2];
    const float* bias = (const float*)d_in[3];
    float* out = (float*)d_out;

    // idempotent, cheap; safe under graph capture (host-side attribute, not a stream op)
    cudaFuncSetAttribute(dcn_kernel, cudaFuncAttributeMaxDynamicSharedMemorySize, SMEM_BYTES);

    // 512 blocks: (row, cout-half); 256 threads = one output row of wo
    dcn_kernel<<<BB*HO*2, 256, SMEM_BYTES>>>(x, off, w, bias, out);
}

// round 2
// speedup vs baseline: 1.4486x; 1.4486x over previous
#include <cuda_runtime.h>
#include <cstdint>

#define BB 2
#define CIN 64
#define HIN 128
#define WIN 256
#define COUTN 64
#define KK 9
#define HO 128
#define WO 256
#define HWIN (HIN*WIN)
#define HWO (HO*WO)
#define WPITCH 68                         // 64 couts + 4 pad (conflict relief, 16B aligned)
#define SW_FLOATS (CIN*KK*WPITCH)         // 39168
#define SS_FLOATS (CIN*WO)                // 16384
#define SMEM_BYTES ((SW_FLOATS + SS_FLOATS)*4)   // 222208 B

extern __shared__ float smem[];

__device__ __forceinline__ unsigned long long dup2(float v) {
    unsigned long long r;
    asm("mov.b64 %0, {%1, %1};" : "=l"(r) : "r"(__float_as_uint(v)));
    return r;
}

__global__ __launch_bounds__(256, 1)
void dcn_gemm(const float* __restrict__ x, const float* __restrict__ off,
              const float* __restrict__ weight, const float* __restrict__ bias,
              float* __restrict__ out)
{
    float* s_w = smem;                    // [576 ck][68] : s_w[ck*68 + cout]
    float* s_S = smem + SW_FLOATS;        // [64 c][256 px]

    const int tid  = threadIdx.x;
    const int ho   = blockIdx.x & (HO-1);
    const int b    = blockIdx.x >> 7;
    const int wid  = tid >> 5;            // cout group: wid*8 .. wid*8+7
    const int lane = tid & 31;            // pixel group: lane*8 .. lane*8+7

    // ---- stage transposed weights (coalesced gmem read, pitched STS) ----
    #pragma unroll 4
    for (int i = tid; i < COUTN*CIN*KK; i += 256) {
        int cout = i / (CIN*KK);
        int ck   = i % (CIN*KK);
        s_w[ck*WPITCH + cout] = weight[i];
    }

    const float* xb   = x + (size_t)b * (CIN*HWIN);
    const float* offp = off + (size_t)b * (2*KK*HWO) + ho*WO + tid;

    unsigned long long acc[4][8];
    #pragma unroll
    for (int i = 0; i < 4; i++)
        #pragma unroll
        for (int j = 0; j < 8; j++) acc[i][j] = 0ULL;

    __syncthreads();

    for (int k = 0; k < KK; k++) {
        // ================= phase A: sample S[c][tid] for this k =================
        {
            const int ki = k / 3, kj = k % 3;
            const float oy = offp[(2*k  )*HWO];
            const float ox = offp[(2*k+1)*HWO];
            const float py = (float)(ho - 1 + ki) + oy;
            const float px = (float)(tid - 1 + kj) + ox;
            const float y0f = floorf(py), x0f = floorf(px);
            const float wy = py - y0f,   wx = px - x0f;
            const int y0 = (int)y0f, x0 = (int)x0f;
            const int y1 = y0 + 1,   x1 = x0 + 1;
            const float vy0 = (y0 >= 0 && y0 < HIN) ? 1.f : 0.f;
            const float vy1 = (y1 >= 0 && y1 < HIN) ? 1.f : 0.f;
            const float vx0 = (x0 >= 0 && x0 < WIN) ? 1.f : 0.f;
            const float vx1 = (x1 >= 0 && x1 < WIN) ? 1.f : 0.f;
            const int ya  = min(max(y0, 0), HIN-1), yb = min(max(y1, 0), HIN-1);
            const int xa  = min(max(x0, 0), WIN-1), xc = min(max(x1, 0), WIN-1);
            const float w00 = (1.f-wy)*(1.f-wx)*vy0*vx0;
            const float w01 = (1.f-wy)*wx      *vy0*vx1;
            const float w10 = wy      *(1.f-wx)*vy1*vx0;
            const float w11 = wy      *wx      *vy1*vx1;
            const float* q00 = xb + ya*WIN + xa;
            const float* q01 = xb + ya*WIN + xc;
            const float* q10 = xb + yb*WIN + xa;
            const float* q11 = xb + yb*WIN + xc;

            #pragma unroll 8
            for (int c = 0; c < CIN; c++) {
                float s = w00 * __ldg(q00 + c*HWIN)
                        + w01 * __ldg(q01 + c*HWIN)
                        + w10 * __ldg(q10 + c*HWIN)
                        + w11 * __ldg(q11 + c*HWIN);
                s_S[c*WO + tid] = s;
            }
        }
        __syncthreads();

        // ================= phase B: GEMM from smem =================
        {
            const float* wbase = s_w + k*WPITCH + (wid << 3);
            const float* sbase = s_S + (lane << 3);
            #pragma unroll 4
            for (int c = 0; c < CIN; c++) {
                const ulonglong2 wA = *(const ulonglong2*)(wbase + c*(KK*WPITCH));      // (w0,w1),(w2,w3)
                const ulonglong2 wB = *(const ulonglong2*)(wbase + c*(KK*WPITCH) + 4);  // (w4,w5),(w6,w7)
                const float4 pA = *(const float4*)(sbase + c*WO);
                const float4 pB = *(const float4*)(sbase + c*WO + 4);
                unsigned long long pd[8];
                pd[0] = dup2(pA.x); pd[1] = dup2(pA.y); pd[2] = dup2(pA.z); pd[3] = dup2(pA.w);
                pd[4] = dup2(pB.x); pd[5] = dup2(pB.y); pd[6] = dup2(pB.z); pd[7] = dup2(pB.w);
                #pragma unroll
                for (int j = 0; j < 8; j++) {
                    asm("fma.rn.f32x2 %0, %1, %2, %0;" : "+l"(acc[0][j]) : "l"(wA.x), "l"(pd[j]));
                    asm("fma.rn.f32x2 %0, %1, %2, %0;" : "+l"(acc[1][j]) : "l"(wA.y), "l"(pd[j]));
                    asm("fma.rn.f32x2 %0, %1, %2, %0;" : "+l"(acc[2][j]) : "l"(wB.x), "l"(pd[j]));
                    asm("fma.rn.f32x2 %0, %1, %2, %0;" : "+l"(acc[3][j]) : "l"(wB.y), "l"(pd[j]));
                }
            }
        }
        __syncthreads();
    }

    // ================= epilogue: bias + packed stores =================
    #pragma unroll
    for (int cp = 0; cp < 4; cp++) {
        const int c0 = (wid << 3) + 2*cp;
        const float b0 = bias[c0];
        const float b1 = bias[c0 + 1];
        float lo[8], hi[8];
        #pragma unroll
        for (int j = 0; j < 8; j++) {
            unsigned int l, h;
            asm("mov.b64 {%0, %1}, %2;" : "=r"(l), "=r"(h) : "l"(acc[cp][j]));
            lo[j] = __uint_as_float(l) + b0;
            hi[j] = __uint_as_float(h) + b1;
        }
        float* o0 = out + ((size_t)(b*COUTN + c0    )*HO + ho)*WO + (lane << 3);
        float* o1 = out + ((size_t)(b*COUTN + c0 + 1)*HO + ho)*WO + (lane << 3);
        *(float4*)(o0    ) = make_float4(lo[0], lo[1], lo[2], lo[3]);
        *(float4*)(o0 + 4) = make_float4(lo[4], lo[5], lo[6], lo[7]);
        *(float4*)(o1    ) = make_float4(hi[0], hi[1], hi[2], hi[3]);
        *(float4*)(o1 + 4) = make_float4(hi[4], hi[5], hi[6], hi[7]);
    }
}

extern "C" void kernel_launch(void* const* d_in, const int* in_sizes, int n_in,
                              void* d_out, int out_size) {
    const float* x    = (const float*)d_in[0];
    const float* off  = (const float*)d_in[1];
    const float* w    = (const float*)d_in[2];
    const float* bias = (const float*)d_in[3];
    float* out = (float*)d_out;

    cudaFuncSetAttribute(dcn_gemm, cudaFuncAttributeMaxDynamicSharedMemorySize, SMEM_BYTES);

    // 256 blocks: one per (b, ho) output row of 256 pixels; 64 couts per block
    dcn_gemm<<<BB*HO, 256, SMEM_BYTES>>>(x, off, w, bias, out);
}

// round 3
// speedup vs baseline: 1.5981x; 1.1032x over previous
#include <cuda_runtime.h>
#include <cstdint>

#define BB 2
#define CIN 64
#define HIN 128
#define WIN 256
#define COUTN 64
#define KK 9
#define HO 128
#define WO 256
#define HWIN (HIN*WIN)
#define HWO (HO*WO)
#define SS_FLOATS (CIN*WO)              // 16384 floats = 64 KB
#define SMEM_BYTES (SS_FLOATS*4)

// Pre-transposed weights: wT[((k*CIN + c)*COUTN) + cout]
__device__ float g_wT[KK*CIN*COUTN];

extern __shared__ float s_S[];          // [64 c][256 px]

__device__ __forceinline__ unsigned long long dup2(float v) {
    unsigned long long r;
    asm("mov.b64 %0, {%1, %1};" : "=l"(r) : "r"(__float_as_uint(v)));
    return r;
}

__global__ void transpose_w(const float* __restrict__ w) {
    int i = blockIdx.x * 256 + threadIdx.x;         // (k, c, cout)
    if (i < KK*CIN*COUTN) {
        int k    = i / (CIN*COUTN);
        int rem  = i % (CIN*COUTN);
        int c    = rem >> 6;
        int cout = rem & 63;
        g_wT[i] = w[cout*(CIN*KK) + c*KK + k];
    }
}

#define FMA4(J, PV)                                                                   \
    {   unsigned long long pd = dup2(PV);                                             \
        asm("fma.rn.f32x2 %0, %1, %2, %0;" : "+l"(acc[0][J]) : "l"(wA.x), "l"(pd));   \
        asm("fma.rn.f32x2 %0, %1, %2, %0;" : "+l"(acc[1][J]) : "l"(wA.y), "l"(pd));   \
        asm("fma.rn.f32x2 %0, %1, %2, %0;" : "+l"(acc[2][J]) : "l"(wB.x), "l"(pd));   \
        asm("fma.rn.f32x2 %0, %1, %2, %0;" : "+l"(acc[3][J]) : "l"(wB.y), "l"(pd)); }

__global__ __launch_bounds__(256, 2)
void dcn_gemm(const float* __restrict__ x, const float* __restrict__ off,
              const float* __restrict__ bias, float* __restrict__ out)
{
    const int tid  = threadIdx.x;
    const int ho   = blockIdx.x & (HO-1);
    const int b    = blockIdx.x >> 7;
    const int wid  = tid >> 5;            // cout group: wid*8 .. wid*8+7
    const int lane = tid & 31;            // pixel group: lane*8 .. lane*8+7

    const float* xb   = x + (size_t)b * (CIN*HWIN);
    const float* offp = off + (size_t)b * (2*KK*HWO) + ho*WO + tid;

    unsigned long long acc[4][8];
    #pragma unroll
    for (int i = 0; i < 4; i++)
        #pragma unroll
        for (int j = 0; j < 8; j++) acc[i][j] = 0ULL;

    for (int k = 0; k < KK; k++) {
        // ===== phase A: sample S[c][tid] for this k =====
        {
            const int ki = k / 3, kj = k % 3;
            const float oy = offp[(2*k  )*HWO];
            const float ox = offp[(2*k+1)*HWO];
            const float py = (float)(ho - 1 + ki) + oy;
            const float px = (float)(tid - 1 + kj) + ox;
            const float y0f = floorf(py), x0f = floorf(px);
            const float wy = py - y0f,   wx = px - x0f;
            const int y0 = (int)y0f, x0 = (int)x0f;
            const int y1 = y0 + 1,   x1 = x0 + 1;
            const float vy0 = (y0 >= 0 && y0 < HIN) ? 1.f : 0.f;
            const float vy1 = (y1 >= 0 && y1 < HIN) ? 1.f : 0.f;
            const float vx0 = (x0 >= 0 && x0 < WIN) ? 1.f : 0.f;
            const float vx1 = (x1 >= 0 && x1 < WIN) ? 1.f : 0.f;
            const int ya  = min(max(y0, 0), HIN-1), yb = min(max(y1, 0), HIN-1);
            const int xa  = min(max(x0, 0), WIN-1), xc = min(max(x1, 0), WIN-1);
            const float w00 = (1.f-wy)*(1.f-wx)*vy0*vx0;
            const float w01 = (1.f-wy)*wx      *vy0*vx1;
            const float w10 = wy      *(1.f-wx)*vy1*vx0;
            const float w11 = wy      *wx      *vy1*vx1;
            const float* q00 = xb + ya*WIN + xa;
            const float* q01 = xb + ya*WIN + xc;
            const float* q10 = xb + yb*WIN + xa;
            const float* q11 = xb + yb*WIN + xc;

            #pragma unroll 8
            for (int c = 0; c < CIN; c++) {
                float s = w00 * __ldg(q00 + c*HWIN)
                        + w01 * __ldg(q01 + c*HWIN)
                        + w10 * __ldg(q10 + c*HWIN)
                        + w11 * __ldg(q11 + c*HWIN);
                s_S[c*WO + tid] = s;
            }
        }
        __syncthreads();

        // ===== phase B: GEMM; weights via warp-broadcast LDG (L1-resident) =====
        {
            const float* wrow  = g_wT + k*(CIN*COUTN) + (wid << 3);
            const float* sbase = s_S + (lane << 3);
            #pragma unroll 4
            for (int c = 0; c < CIN; c++) {
                const ulonglong2 wA = __ldg((const ulonglong2*)(wrow + c*COUTN));      // couts 0-3
                const ulonglong2 wB = __ldg((const ulonglong2*)(wrow + c*COUTN + 4));  // couts 4-7
                const float4 pA = *(const float4*)(sbase + c*WO);
                const float4 pB = *(const float4*)(sbase + c*WO + 4);
                FMA4(0, pA.x) FMA4(1, pA.y) FMA4(2, pA.z) FMA4(3, pA.w)
                FMA4(4, pB.x) FMA4(5, pB.y) FMA4(6, pB.z) FMA4(7, pB.w)
            }
        }
        __syncthreads();
    }

    // ===== epilogue: bias + packed stores =====
    #pragma unroll
    for (int cp = 0; cp < 4; cp++) {
        const int c0 = (wid << 3) + 2*cp;
        const float b0 = bias[c0];
        const float b1 = bias[c0 + 1];
        float lo[8], hi[8];
        #pragma unroll
        for (int j = 0; j < 8; j++) {
            unsigned int l, h;
            asm("mov.b64 {%0, %1}, %2;" : "=r"(l), "=r"(h) : "l"(acc[cp][j]));
            lo[j] = __uint_as_float(l) + b0;
            hi[j] = __uint_as_float(h) + b1;
        }
        float* o0 = out + ((size_t)(b*COUTN + c0    )*HO + ho)*WO + (lane << 3);
        float* o1 = out + ((size_t)(b*COUTN + c0 + 1)*HO + ho)*WO + (lane << 3);
        *(float4*)(o0    ) = make_float4(lo[0], lo[1], lo[2], lo[3]);
        *(float4*)(o0 + 4) = make_float4(lo[4], lo[5], lo[6], lo[7]);
        *(float4*)(o1    ) = make_float4(hi[0], hi[1], hi[2], hi[3]);
        *(float4*)(o1 + 4) = make_float4(hi[4], hi[5], hi[6], hi[7]);
    }
}

extern "C" void kernel_launch(void* const* d_in, const int* in_sizes, int n_in,
                              void* d_out, int out_size) {
    const float* x    = (const float*)d_in[0];
    const float* off  = (const float*)d_in[1];
    const float* w    = (const float*)d_in[2];
    const float* bias = (const float*)d_in[3];
    float* out = (float*)d_out;

    cudaFuncSetAttribute(dcn_gemm, cudaFuncAttributeMaxDynamicSharedMemorySize, SMEM_BYTES);

    transpose_w<<<(KK*CIN*COUTN + 255)/256, 256>>>(w);
    // 256 blocks: one per (b, ho) row; 2 CTAs/SM -> single wave
    dcn_gemm<<<BB*HO, 256, SMEM_BYTES>>>(x, off, bias, out);
}

// round 4
// speedup vs baseline: 1.9943x; 1.2479x over previous
#include <cuda_runtime.h>
#include <cstdint>

#define BB 2
#define CIN 64
#define HIN 128
#define WIN 256
#define COUTN 64
#define KK 9
#define HO 128
#define WO 256
#define HWIN (HIN*WIN)
#define HWO (HO*WO)
#define SS_FLOATS (WO*CIN)              // 16384 floats, swizzled [px][c]
#define SD_FLOATS (WO*8)                // descriptors: 4 int offs + 4 weights per px
#define SMEM_BYTES ((SS_FLOATS + SD_FLOATS)*4)   // 73728 B

// NHWC copy of x: g_xt[((b*HIN + h)*WIN + w)*64 + c]
__device__ float g_xt[(size_t)BB*HIN*WIN*CIN];
// Transposed weights: g_wT[((k*CIN + c)*COUTN) + cout]
__device__ float g_wT[KK*CIN*COUTN];

__device__ __forceinline__ unsigned long long dup2(float v) {
    unsigned long long r;
    asm("mov.b64 %0, {%1, %1};" : "=l"(r) : "r"(__float_as_uint(v)));
    return r;
}

__global__ void transpose_w(const float* __restrict__ w) {
    int i = blockIdx.x * 256 + threadIdx.x;
    if (i < KK*CIN*COUTN) {
        int k    = i / (CIN*COUTN);
        int rem  = i % (CIN*COUTN);
        int c    = rem >> 6;
        int cout = rem & 63;
        g_wT[i] = w[cout*(CIN*KK) + c*KK + k];
    }
}

// Tiled NCHW -> NHWC transpose: block = (b, h, 32-wide w tile), all 64 channels
__global__ __launch_bounds__(256)
void transpose_x(const float* __restrict__ x) {
    __shared__ float t[CIN][33];
    const int bw = blockIdx.x & 7;
    const int h  = (blockIdx.x >> 3) & (HIN-1);
    const int b  = blockIdx.x >> 10;
    const int w0 = bw << 5;
    const int tw = threadIdx.x & 31, tc = threadIdx.x >> 5;   // 32 w x 8 c-rows
    const float* src = x + ((size_t)(b*CIN)*HIN + h)*WIN + w0 + tw;
    #pragma unroll
    for (int c = tc; c < CIN; c += 8) t[c][tw] = src[(size_t)c*HWIN];
    __syncthreads();
    const int c   = threadIdx.x & 63;
    const int wg  = threadIdx.x >> 6;                          // 4 groups x 8 w
    float* dst = g_xt + ((size_t)((b*HIN + h)*WIN) + w0)*CIN + c;
    #pragma unroll
    for (int i = 0; i < 8; i++) {
        int wl = (wg << 3) + i;
        dst[(size_t)wl*CIN] = t[c][wl];
    }
}

#define FMA4CH(WA, WB, COMP, I)                                                        \
    {   unsigned long long pd = dup2(COMP);                                            \
        asm("fma.rn.f32x2 %0, %1, %2, %0;" : "+l"(acc[0][I]) : "l"((WA).x), "l"(pd));  \
        asm("fma.rn.f32x2 %0, %1, %2, %0;" : "+l"(acc[1][I]) : "l"((WA).y), "l"(pd));  \
        asm("fma.rn.f32x2 %0, %1, %2, %0;" : "+l"(acc[2][I]) : "l"((WB).x), "l"(pd));  \
        asm("fma.rn.f32x2 %0, %1, %2, %0;" : "+l"(acc[3][I]) : "l"((WB).y), "l"(pd)); }

__global__ __launch_bounds__(256, 2)
void dcn_main(const float* __restrict__ off, const float* __restrict__ bias,
              float* __restrict__ out)
{
    extern __shared__ float smem[];
    float* s_S    = smem;                 // [256 px][64 c], chunk-swizzled
    float* s_desc = smem + SS_FLOATS;     // [256 px][8]

    const int tid  = threadIdx.x;
    const int ho   = blockIdx.x & (HO-1);
    const int b    = blockIdx.x >> 7;
    const int warp = tid >> 5;            // cout group (GEMM) / pixel group (sampling)
    const int lane = tid & 31;
    const int m    = lane & 15;           // channel chunk in coop sampling
    const int hp   = lane >> 4;           // which pixel of the pair

    const float* offp = off + (size_t)b*(2*KK*HWO) + ho*WO + tid;
    const float* xb   = g_xt + (size_t)b*(HIN*WIN*CIN);

    unsigned long long acc[4][8];
    #pragma unroll
    for (int i = 0; i < 4; i++)
        #pragma unroll
        for (int j = 0; j < 8; j++) acc[i][j] = 0ULL;

    #pragma unroll 1
    for (int k = 0; k < KK; k++) {
        // ---- pre-pass: per-pixel bilinear descriptor -> smem ----
        {
            const int ki = k / 3, kj = k % 3;
            const float oy = offp[(2*k  )*HWO];
            const float ox = offp[(2*k+1)*HWO];
            const float py = (float)(ho - 1 + ki) + oy;
            const float px = (float)(tid - 1 + kj) + ox;
            const float y0f = floorf(py), x0f = floorf(px);
            const float wy = py - y0f,   wx = px - x0f;
            const int y0 = (int)y0f, x0 = (int)x0f;
            const int y1 = y0 + 1,   x1 = x0 + 1;
            const float vy0 = (y0 >= 0 && y0 < HIN) ? 1.f : 0.f;
            const float vy1 = (y1 >= 0 && y1 < HIN) ? 1.f : 0.f;
            const float vx0 = (x0 >= 0 && x0 < WIN) ? 1.f : 0.f;
            const float vx1 = (x1 >= 0 && x1 < WIN) ? 1.f : 0.f;
            const int ya = min(max(y0, 0), HIN-1), yb = min(max(y1, 0), HIN-1);
            const int xa = min(max(x0, 0), WIN-1), xc = min(max(x1, 0), WIN-1);
            ((int4*)s_desc)[tid*2] = make_int4(ya*WIN + xa, ya*WIN + xc,
                                               yb*WIN + xa, yb*WIN + xc);
            ((float4*)s_desc)[tid*2 + 1] =
                make_float4((1.f-wy)*(1.f-wx)*vy0*vx0, (1.f-wy)*wx*vy0*vx1,
                            wy*(1.f-wx)*vy1*vx0,       wy*wx*vy1*vx1);
        }
        __syncthreads();

        // ---- phase A: cooperative channel-dense sampling (NHWC) ----
        {
            const float* xm = xb + (m << 2);
            #pragma unroll 4
            for (int t = 0; t < 16; t++) {
                const int p = (warp << 5) + (t << 1) + hp;
                const int4   o  = ((const int4*)s_desc)[p << 1];
                const float4 wv = ((const float4*)s_desc)[(p << 1) + 1];
                const float4 v00 = __ldg((const float4*)(xm + (size_t)o.x*CIN));
                const float4 v01 = __ldg((const float4*)(xm + (size_t)o.y*CIN));
                const float4 v10 = __ldg((const float4*)(xm + (size_t)o.z*CIN));
                const float4 v11 = __ldg((const float4*)(xm + (size_t)o.w*CIN));
                float4 s;
                s.x = wv.x*v00.x + wv.y*v01.x + wv.z*v10.x + wv.w*v11.x;
                s.y = wv.x*v00.y + wv.y*v01.y + wv.z*v10.y + wv.w*v11.y;
                s.z = wv.x*v00.z + wv.y*v01.z + wv.z*v10.z + wv.w*v11.z;
                s.w = wv.x*v00.w + wv.y*v01.w + wv.z*v10.w + wv.w*v11.w;
                *(float4*)(s_S + (p << 6) + ((m ^ (p & 7)) << 2)) = s;
            }
        }
        __syncthreads();

        // ---- phase B: GEMM (8 couts x 8 px per thread) ----
        {
            const float* wk = g_wT + k*(CIN*COUTN) + (warp << 3);
            const float* sb = s_S + (lane << 6);
            const int sw7 = lane & 7;
            #pragma unroll 4
            for (int j = 0; j < 16; j++) {
                const float* wc = wk + (j << 2)*COUTN;
                const ulonglong2 w0A = __ldg((const ulonglong2*)(wc          ));
                const ulonglong2 w0B = __ldg((const ulonglong2*)(wc       + 4));
                const ulonglong2 w1A = __ldg((const ulonglong2*)(wc +   64   ));
                const ulonglong2 w1B = __ldg((const ulonglong2*)(wc +   64+ 4));
                const ulonglong2 w2A = __ldg((const ulonglong2*)(wc +  128   ));
                const ulonglong2 w2B = __ldg((const ulonglong2*)(wc +  128+ 4));
                const ulonglong2 w3A = __ldg((const ulonglong2*)(wc +  192   ));
                const ulonglong2 w3B = __ldg((const ulonglong2*)(wc +  192+ 4));
                const float* sj = sb + ((j ^ sw7) << 2);
                #pragma unroll
                for (int i = 0; i < 8; i++) {
                    const float4 pv = *(const float4*)(sj + (i << 11));
                    FMA4CH(w0A, w0B, pv.x, i)
                    FMA4CH(w1A, w1B, pv.y, i)
                    FMA4CH(w2A, w2B, pv.z, i)
                    FMA4CH(w3A, w3B, pv.w, i)
                }
            }
        }
        __syncthreads();
    }

    // ---- epilogue: bias + stores (coalesced per cout row) ----
    #pragma unroll
    for (int cp = 0; cp < 4; cp++) {
        const int c0 = (warp << 3) + 2*cp;
        const float b0 = bias[c0];
        const float b1 = bias[c0 + 1];
        float* o0 = out + ((size_t)(b*COUTN + c0    )*HO + ho)*WO + lane;
        float* o1 = out + ((size_t)(b*COUTN + c0 + 1)*HO + ho)*WO + lane;
        #pragma unroll
        for (int i = 0; i < 8; i++) {
            unsigned int l, h;
            asm("mov.b64 {%0, %1}, %2;" : "=r"(l), "=r"(h) : "l"(acc[cp][i]));
            o0[i << 5] = __uint_as_float(l) + b0;
            o1[i << 5] = __uint_as_float(h) + b1;
        }
    }
}

extern "C" void kernel_launch(void* const* d_in, const int* in_sizes, int n_in,
                              void* d_out, int out_size) {
    const float* x    = (const float*)d_in[0];
    const float* off  = (const float*)d_in[1];
    const float* w    = (const float*)d_in[2];
    const float* bias = (const float*)d_in[3];
    float* out = (float*)d_out;

    cudaFuncSetAttribute(dcn_main, cudaFuncAttributeMaxDynamicSharedMemorySize, SMEM_BYTES);

    transpose_w<<<(KK*CIN*COUTN + 255)/256, 256>>>(w);
    transpose_x<<<BB*HIN*(WIN/32), 256>>>(x);
    dcn_main<<<BB*HO, 256, SMEM_BYTES>>>(off, bias, out);
}

// round 6
// speedup vs baseline: 3.7328x; 1.8717x over previous
#include <cuda_runtime.h>
#include <cuda_bf16.h>
#include <cstdint>

#define BB 2
#define CIN 64
#define HIN 128
#define WIN 256
#define COUTN 64
#define KK 9
#define HO 128
#define WO 256
#define HWIN (HIN*WIN)
#define HWO (HO*WO)

// smem layout (bytes)
#define SMEM_DESC 0              // 256 px * 32 B = 8192
#define SMEM_WH   8192           // 64 cout * 128 B = 8192
#define SMEM_WL   16384          // 8192
#define SMEM_SHI  24576          // 256 px * 128 B = 32768
#define SMEM_SLO  57344          // 32768
#define SMEM_BYTES 90112         // 88 KB -> 2 CTAs/SM

// device globals
__device__ float         g_xt[(size_t)BB*HIN*WIN*CIN];   // NHWC x
__device__ __nv_bfloat16 g_wh[KK*COUTN*CIN];             // [k][cout][c]
__device__ __nv_bfloat16 g_wl[KK*COUTN*CIN];

__device__ __forceinline__ uint32_t smem_u32(const void* p) {
    uint32_t a;
    asm("{ .reg .u64 t; cvta.to.shared.u64 t, %1; cvt.u32.u64 %0, t; }" : "=r"(a) : "l"(p));
    return a;
}
#define SWZ128(o) ((o) ^ (((o) >> 3) & 0x70))

#define LDSM4(R, ADDR) \
    asm volatile("ldmatrix.sync.aligned.m8n8.x4.shared.b16 {%0,%1,%2,%3}, [%4];" \
        : "=r"((R)[0]), "=r"((R)[1]), "=r"((R)[2]), "=r"((R)[3]) : "r"(ADDR))
#define LDSM2(R, ADDR) \
    asm volatile("ldmatrix.sync.aligned.m8n8.x2.shared.b16 {%0,%1}, [%2];" \
        : "=r"((R)[0]), "=r"((R)[1]) : "r"(ADDR))
#define MMA16816(D, A, Bv) \
    asm volatile("mma.sync.aligned.m16n8k16.row.col.f32.bf16.bf16.f32 " \
        "{%0,%1,%2,%3}, {%4,%5,%6,%7}, {%8,%9}, {%0,%1,%2,%3};" \
        : "+f"((D)[0]), "+f"((D)[1]), "+f"((D)[2]), "+f"((D)[3]) \
        : "r"((A)[0]), "r"((A)[1]), "r"((A)[2]), "r"((A)[3]), "r"((Bv)[0]), "r"((Bv)[1]))

// ---------- prep kernels ----------
__global__ void split_w(const float* __restrict__ w) {
    int i = blockIdx.x * 256 + threadIdx.x;          // [k][cout][c]
    if (i < KK*COUTN*CIN) {
        int k    = i / (COUTN*CIN);
        int rem  = i % (COUTN*CIN);
        int cout = rem >> 6;
        int c    = rem & 63;
        float v = w[cout*(CIN*KK) + c*KK + k];
        __nv_bfloat16 h = __float2bfloat16_rn(v);
        g_wh[i] = h;
        g_wl[i] = __float2bfloat16_rn(v - __bfloat162float(h));
    }
}

__global__ __launch_bounds__(256)
void transpose_x(const float* __restrict__ x) {
    __shared__ float t[CIN][33];
    const int bw = blockIdx.x & 7;
    const int h  = (blockIdx.x >> 3) & (HIN-1);
    const int b  = blockIdx.x >> 10;
    const int w0 = bw << 5;
    const int tw = threadIdx.x & 31, tc = threadIdx.x >> 5;
    const float* src = x + ((size_t)(b*CIN)*HIN + h)*WIN + w0 + tw;
    #pragma unroll
    for (int c = tc; c < CIN; c += 8) t[c][tw] = src[(size_t)c*HWIN];
    __syncthreads();
    const int c  = threadIdx.x & 63;
    const int wg = threadIdx.x >> 6;
    float* dst = g_xt + ((size_t)((b*HIN + h)*WIN) + w0)*CIN + c;
    #pragma unroll
    for (int i = 0; i < 8; i++) {
        int wl = (wg << 3) + i;
        dst[(size_t)wl*CIN] = t[c][wl];
    }
}

// ---------- main kernel ----------
__global__ __launch_bounds__(256, 2)
void dcn_main(const float* __restrict__ off, const float* __restrict__ bias,
              float* __restrict__ out)
{
    extern __shared__ char smem[];
    const uint32_t sb = smem_u32(smem);
    float* s_desc = (float*)(smem + SMEM_DESC);

    const int tid  = threadIdx.x;
    const int ho   = blockIdx.x & (HO-1);
    const int b    = blockIdx.x >> 7;
    const int warp = tid >> 5;            // pixel group px [warp*32, warp*32+32)
    const int lane = tid & 31;
    const int m    = lane & 15;           // channel chunk (4 ch) in sampling
    const int hp   = lane >> 4;

    const float* offp = off + (size_t)b*(2*KK*HWO) + ho*WO + tid;
    const float* xb   = g_xt + (size_t)b*(HIN*WIN*CIN);

    float acc[2][8][4];
    #pragma unroll
    for (int i = 0; i < 2; i++)
        #pragma unroll
        for (int j = 0; j < 8; j++)
            #pragma unroll
            for (int q = 0; q < 4; q++) acc[i][j][q] = 0.f;

    // ldmatrix lane-derived bases
    const int arow0 = (warp << 5) + (lane & 15);        // A row, mt=0 (+16 for mt=1)
    const uint32_t a_ch = (uint32_t)(lane >> 4) << 4;   // 0 / 16 B
    const int brow0 = lane & 7;                         // B row within n-tile
    const uint32_t b_ch = (uint32_t)((lane >> 3) & 1) << 4;

    for (int k = 0; k < KK; k++) {
        __syncthreads();   // previous mma's ldmatrix reads done before overwrite

        // ---- stage this k's split weights (SW128 rows of 128 B) ----
        {
            const uint4* srcH = (const uint4*)(g_wh + k*(COUTN*CIN));
            const uint4* srcL = (const uint4*)(g_wl + k*(COUTN*CIN));
            #pragma unroll
            for (int u = tid; u < 512; u += 256) {
                uint32_t o  = u << 4;
                uint32_t so = SWZ128(o);
                *(uint4*)(smem + SMEM_WH + so) = srcH[u];
                *(uint4*)(smem + SMEM_WL + so) = srcL[u];
            }
        }

        // ---- per-pixel bilinear descriptor ----
        {
            const int ki = k / 3, kj = k % 3;
            const float oy = offp[(2*k  )*HWO];
            const float ox = offp[(2*k+1)*HWO];
            const float py = (float)(ho - 1 + ki) + oy;
            const float px = (float)(tid - 1 + kj) + ox;
            const float y0f = floorf(py), x0f = floorf(px);
            const float wy = py - y0f,   wx = px - x0f;
            const int y0 = (int)y0f, x0 = (int)x0f;
            const int y1 = y0 + 1,   x1 = x0 + 1;
            const float vy0 = (y0 >= 0 && y0 < HIN) ? 1.f : 0.f;
            const float vy1 = (y1 >= 0 && y1 < HIN) ? 1.f : 0.f;
            const float vx0 = (x0 >= 0 && x0 < WIN) ? 1.f : 0.f;
            const float vx1 = (x1 >= 0 && x1 < WIN) ? 1.f : 0.f;
            const int ya = min(max(y0, 0), HIN-1), yb = min(max(y1, 0), HIN-1);
            const int xa = min(max(x0, 0), WIN-1), xc = min(max(x1, 0), WIN-1);
            ((int4*)s_desc)[tid*2] = make_int4(ya*WIN + xa, ya*WIN + xc,
                                               yb*WIN + xa, yb*WIN + xc);
            ((float4*)s_desc)[tid*2 + 1] =
                make_float4((1.f-wy)*(1.f-wx)*vy0*vx0, (1.f-wy)*wx*vy0*vx1,
                            wy*(1.f-wx)*vy1*vx0,       wy*wx*vy1*vx1);
        }
        __syncthreads();

        // ---- phase A: channel-dense sampling -> bf16 hi/lo tiles [256px][64c] ----
        {
            const float* xm = xb + (m << 2);
            #pragma unroll 4
            for (int t = 0; t < 16; t++) {
                const int p = (warp << 5) + (t << 1) + hp;
                const int4   o  = ((const int4*)s_desc)[p << 1];
                const float4 wv = ((const float4*)s_desc)[(p << 1) + 1];
                const float4 v00 = __ldg((const float4*)(xm + (size_t)o.x*CIN));
                const float4 v01 = __ldg((const float4*)(xm + (size_t)o.y*CIN));
                const float4 v10 = __ldg((const float4*)(xm + (size_t)o.z*CIN));
                const float4 v11 = __ldg((const float4*)(xm + (size_t)o.w*CIN));
                float4 s;
                s.x = wv.x*v00.x + wv.y*v01.x + wv.z*v10.x + wv.w*v11.x;
                s.y = wv.x*v00.y + wv.y*v01.y + wv.z*v10.y + wv.w*v11.y;
                s.z = wv.x*v00.z + wv.y*v01.z + wv.z*v10.z + wv.w*v11.z;
                s.w = wv.x*v00.w + wv.y*v01.w + wv.z*v10.w + wv.w*v11.w;

                __nv_bfloat162 h01 = __floats2bfloat162_rn(s.x, s.y);
                __nv_bfloat162 h23 = __floats2bfloat162_rn(s.z, s.w);
                __nv_bfloat162 l01 = __floats2bfloat162_rn(s.x - __bfloat162float(h01.x),
                                                           s.y - __bfloat162float(h01.y));
                __nv_bfloat162 l23 = __floats2bfloat162_rn(s.z - __bfloat162float(h23.x),
                                                           s.w - __bfloat162float(h23.y));
                uint32_t bo = (uint32_t)(p << 7) + (m << 3);   // p*128 + m*8
                uint32_t so = SWZ128(bo);
                *(uint2*)(smem + SMEM_SHI + so) =
                    make_uint2(*(uint32_t*)&h01, *(uint32_t*)&h23);
                *(uint2*)(smem + SMEM_SLO + so) =
                    make_uint2(*(uint32_t*)&l01, *(uint32_t*)&l23);
            }
        }
        __syncthreads();

        // ---- phase B: ldmatrix + bf16 HMMA (3-term fp32 split) ----
        #pragma unroll
        for (int kc = 0; kc < 4; kc++) {
            const uint32_t koff = (uint32_t)kc << 5;
            uint32_t ah[2][4], al[2][4];
            #pragma unroll
            for (int mt = 0; mt < 2; mt++) {
                const int row = arow0 + (mt << 4);
                const uint32_t addr = sb + (uint32_t)(row << 7)
                                    + ((koff + a_ch) ^ ((uint32_t)(row & 7) << 4));
                LDSM4(ah[mt], addr + SMEM_SHI);
                LDSM4(al[mt], addr + SMEM_SLO);
            }
            #pragma unroll
            for (int nt = 0; nt < 8; nt++) {
                const int row = (nt << 3) + brow0;
                const uint32_t addr = sb + (uint32_t)(row << 7)
                                    + ((koff + b_ch) ^ ((uint32_t)(row & 7) << 4));
                uint32_t bh[2], bl[2];
                LDSM2(bh, addr + SMEM_WH);
                LDSM2(bl, addr + SMEM_WL);
                #pragma unroll
                for (int mt = 0; mt < 2; mt++) {
                    MMA16816(acc[mt][nt], ah[mt], bh);
                    MMA16816(acc[mt][nt], ah[mt], bl);
                    MMA16816(acc[mt][nt], al[mt], bh);
                }
            }
        }
    }

    // ---- epilogue: bias + direct stores ----
    float* ob = out + (size_t)b*COUTN*HWO + ho*WO;
    #pragma unroll
    for (int nt = 0; nt < 8; nt++) {
        const int c0 = (nt << 3) + ((lane & 3) << 1);
        const float b0 = __ldg(bias + c0);
        const float b1 = __ldg(bias + c0 + 1);
        #pragma unroll
        for (int mt = 0; mt < 2; mt++) {
            const int px = (warp << 5) + (mt << 4) + (lane >> 2);
            float* p0 = ob + (size_t)c0*HWO + px;
            float* p1 = p0 + HWO;
            p0[0] = acc[mt][nt][0] + b0;
            p1[0] = acc[mt][nt][1] + b1;
            p0[8] = acc[mt][nt][2] + b0;
            p1[8] = acc[mt][nt][3] + b1;
        }
    }
}

extern "C" void kernel_launch(void* const* d_in, const int* in_sizes, int n_in,
                              void* d_out, int out_size) {
    const float* x    = (const float*)d_in[0];
    const float* off  = (const float*)d_in[1];
    const float* w    = (const float*)d_in[2];
    const float* bias = (const float*)d_in[3];
    float* out = (float*)d_out;

    cudaFuncSetAttribute(dcn_main, cudaFuncAttributeMaxDynamicSharedMemorySize, SMEM_BYTES);

    split_w<<<(KK*COUTN*CIN + 255)/256, 256>>>(w);
    transpose_x<<<BB*HIN*(WIN/32), 256>>>(x);
    dcn_main<<<BB*HO, 256, SMEM_BYTES>>>(off, bias, out);
}